// round 7
// baseline (speedup 1.0000x reference)
#include <cuda_runtime.h>
#include <math.h>

#define FRAME      480
#define NHALF      480
#define FREQ       481
#define NB_ERB     32
#define NB_DF      96
#define ALPHA_F    0.99f
#define ONE_MINUS_ALPHA 0.01f
#define WNORM_F    (1.0f/960.0f)
#define T_MAX      65536
#define CHUNKS     1024

// ---------------- compile-time trig (double Taylor, |x| <= ~pi) ----------------
constexpr double PI_D = 3.14159265358979323846;
constexpr double tsin(double x){
    double t = x, s = x;
    for (int n = 1; n <= 11; n++){ t *= -x*x/((2.0*n)*(2.0*n+1.0)); s += t; }
    return s;
}
constexpr double tcos(double x){
    double t = 1.0, s = 1.0;
    for (int n = 1; n <= 11; n++){ t *= -x*x/((2.0*n-1.0)*(2.0*n)); s += t; }
    return s;
}

struct TabF2_480 { float2 v[480]; };
struct TabF2_128 { float2 v[128]; };
struct TabF2_481 { float2 v[481]; };

constexpr TabF2_480 mk_tw480(){
    TabF2_480 t{};
    for (int idx = 0; idx < 480; idx++){
        int k1 = idx / 32, l = idx % 32;
        int m = (l * k1) % 480;
        if (m > 240) m -= 480;
        double ang = -2.0 * PI_D * (double)m / 480.0;
        t.v[idx] = { (float)tcos(ang), (float)tsin(ang) };
    }
    return t;
}
constexpr TabF2_128 mk_shtw(){
    TabF2_128 t{};
    for (int idx = 0; idx < 128; idx++){
        int j = idx / 32, l = idx % 32;
        int h = 16 >> j;
        if (l & h){
            double ang = -2.0 * PI_D * (double)(l & (h-1)) / (double)(2*h);
            t.v[idx] = { (float)tcos(ang), (float)tsin(ang) };
        } else {
            t.v[idx] = { 1.0f, 0.0f };
        }
    }
    return t;
}
constexpr TabF2_480 mk_win2(){
    TabF2_480 t{};
    const double sc = 0.5 / 960.0;   // 0.5 * WNORM folded in
    for (int j = 0; j < 480; j++){
        double a0 = tsin(0.5 * PI_D * (2*j + 0.5) / 480.0);
        double a1 = tsin(0.5 * PI_D * (2*j + 1.5) / 480.0);
        t.v[j] = { (float)(sc * tsin(0.5 * PI_D * a0 * a0)),
                   (float)(sc * tsin(0.5 * PI_D * a1 * a1)) };
    }
    return t;
}
constexpr TabF2_481 mk_rec(){
    TabF2_481 t{};
    for (int k = 0; k <= 480; k++){
        double ang = -PI_D * (double)k / 480.0;
        t.v[k] = { (float)tcos(ang), (float)tsin(ang) };
    }
    return t;
}

__device__ const TabF2_480 g_tw480_c = mk_tw480();
__device__ const TabF2_128 g_shtw_c  = mk_shtw();
__device__ const TabF2_480 g_win2_c  = mk_win2();
__device__ const TabF2_481 g_rec_c   = mk_rec();

// ---------------- static device scratch ----------------
__device__ float  g_erb[T_MAX * NB_ERB];
__device__ float  g_mag[T_MAX * NB_DF];
__device__ float  g_carryE[CHUNKS * NB_ERB];
__device__ float  g_inE[CHUNKS * NB_ERB];
__device__ float  g_carryS[CHUNKS * NB_DF];
__device__ float  g_inS[CHUNKS * NB_DF];

__constant__ int c_bandOff[NB_ERB] =
 {0,2,4,6,8,10,12,14,16,18,20,22,24,26,31,36,43,50,58,68,80,93,108,126,146,170,198,229,266,308,358,414};
__constant__ int c_bandCnt[NB_ERB] =
 {2,2,2,2,2,2,2,2,2,2,2,2,2,5,5,7,7,8,10,12,13,15,18,20,24,28,31,37,42,50,56,67};
__constant__ float c_bandInv[NB_ERB] =
 {0.5f,0.5f,0.5f,0.5f,0.5f,0.5f,0.5f,0.5f,0.5f,0.5f,0.5f,0.5f,0.5f,
  0.2f,0.2f,1.f/7,1.f/7,0.125f,0.1f,1.f/12,1.f/13,1.f/15,1.f/18,0.05f,
  1.f/24,1.f/28,1.f/31,1.f/37,1.f/42,0.02f,1.f/56,1.f/67};

// ---------------- complex helpers ----------------
__device__ __forceinline__ float2 cmul(float2 a, float2 b){
    return make_float2(fmaf(a.x,b.x,-a.y*b.y), fmaf(a.x,b.y, a.y*b.x));
}

// Winograd radix-3
__device__ __forceinline__ void dft3w(float2 x0, float2 x1, float2 x2,
                                      float2& X0, float2& X1, float2& X2){
    float t1x = x1.x + x2.x, t1y = x1.y + x2.y;
    float t2x = x1.x - x2.x, t2y = x1.y - x2.y;
    X0 = make_float2(x0.x + t1x, x0.y + t1y);
    float mx = fmaf(-0.5f, t1x, x0.x), my = fmaf(-0.5f, t1y, x0.y);
    float vx = 0.86602540378f * t2x,   vy = 0.86602540378f * t2y;
    X1 = make_float2(mx + vy, my - vx);
    X2 = make_float2(mx - vy, my + vx);
}
// Winograd radix-5
__device__ __forceinline__ void dft5w(float2 x0, float2 x1, float2 x2, float2 x3, float2 x4,
                                      float2& X0, float2& X1, float2& X2, float2& X3, float2& X4){
    const float s1 = 0.95105651630f, s2 = 0.58778525229f;
    float t1x=x1.x+x4.x, t1y=x1.y+x4.y;
    float t2x=x1.x-x4.x, t2y=x1.y-x4.y;
    float t3x=x2.x+x3.x, t3y=x2.y+x3.y;
    float t4x=x2.x-x3.x, t4y=x2.y-x3.y;
    float t5x=t1x+t3x,   t5y=t1y+t3y;
    X0 = make_float2(x0.x+t5x, x0.y+t5y);
    float px = fmaf(-0.25f,t5x,x0.x), py = fmaf(-0.25f,t5y,x0.y);
    float t6x=t1x-t3x,   t6y=t1y-t3y;
    float qx = 0.55901699437f*t6x,    qy = 0.55901699437f*t6y;
    float Px=px+qx, Py=py+qy, Qx=px-qx, Qy=py-qy;
    float Rx = fmaf(s2,t4x, s1*t2x),  Ry = fmaf(s2,t4y, s1*t2y);
    float Sx = fmaf(-s1,t4x, s2*t2x), Sy = fmaf(-s1,t4y, s2*t2y);
    X1 = make_float2(Px+Ry, Py-Rx);
    X4 = make_float2(Px-Ry, Py+Rx);
    X2 = make_float2(Qx+Sy, Qy-Sx);
    X3 = make_float2(Qx-Sy, Qy+Sx);
}

// ---------------- FFT: one warp per frame, register-resident ----------------
__global__ __launch_bounds__(128) void fft_kernel(const float* __restrict__ audio,
                                                  float* __restrict__ out, int T){
    __shared__ float2 sZ[4][NHALF];
    __shared__ float  smag[4][FREQ];
    int w = threadIdx.x >> 5;
    int l = threadIdx.x & 31;
    int t = blockIdx.x * 4 + w;
    if (t >= T) return;

    const float2* audio2 = (const float2*)audio;
    const float2* g_tw480 = g_tw480_c.v;
    const float2* g_shtw  = g_shtw_c.v;
    const float2* g_win2  = g_win2_c.v;
    const float2* g_rec   = g_rec_c.v;
    long base2 = ((long)t - 1) * 240;

    // load + window (0.5*WNORM folded)
    float2 z[15];
    #pragma unroll
    for (int m = 0; m < 15; m++){
        long i2 = base2 + l + 32*m;
        float2 x = (i2 >= 0) ? audio2[i2] : make_float2(0.f,0.f);
        float2 ww = g_win2[l + 32*m];
        z[m] = make_float2(x.x*ww.x, x.y*ww.y);
    }

    // ---- radix-15 (3x5 Winograd) in registers
    float2 B[15];
    {
        float2 G0[5], G1[5], G2[5];
        #pragma unroll
        for (int b = 0; b < 5; b++)
            dft3w(z[b], z[5+b], z[10+b], G0[b], G1[b], G2[b]);
        dft5w(G0[0],G0[1],G0[2],G0[3],G0[4], B[0],B[3],B[6],B[9],B[12]);
        G1[1] = cmul(G1[1], make_float2( 0.91354545764f,-0.40673664308f));
        G1[2] = cmul(G1[2], make_float2( 0.66913060636f,-0.74314482548f));
        G1[3] = cmul(G1[3], make_float2( 0.30901699437f,-0.95105651630f));
        G1[4] = cmul(G1[4], make_float2(-0.10452846327f,-0.99452189537f));
        dft5w(G1[0],G1[1],G1[2],G1[3],G1[4], B[1],B[4],B[7],B[10],B[13]);
        G2[1] = cmul(G2[1], make_float2( 0.66913060636f,-0.74314482548f));
        G2[2] = cmul(G2[2], make_float2(-0.10452846327f,-0.99452189537f));
        G2[3] = cmul(G2[3], make_float2(-0.80901699437f,-0.58778525229f));
        G2[4] = cmul(G2[4], make_float2(-0.97814760073f, 0.20791169082f));
        dft5w(G2[0],G2[1],G2[2],G2[3],G2[4], B[2],B[5],B[8],B[11],B[14]);
    }

    // ---- four-step twiddle
    #pragma unroll
    for (int k1 = 1; k1 < 15; k1++)
        B[k1] = cmul(B[k1], g_tw480[k1*32 + l]);

    // ---- 32-pt cross-lane DFT: 5 radix-2 DIF shuffle stages
    // j<3: table twiddle; j==3: twiddle is {1,-i} -> swap/negate select; j==4: identity
    bool rot3 = ((l & 3) == 3);
    #pragma unroll
    for (int j = 0; j < 5; j++){
        int h = 16 >> j;
        float sgn = (l & h) ? -1.f : 1.f;
        float2 tw = (j < 3) ? g_shtw[j*32 + l] : make_float2(1.f, 0.f);
        #pragma unroll
        for (int k1 = 0; k1 < 15; k1++){
            float px = __shfl_xor_sync(0xffffffffu, B[k1].x, h);
            float py = __shfl_xor_sync(0xffffffffu, B[k1].y, h);
            float nx = fmaf(sgn, B[k1].x, px), ny = fmaf(sgn, B[k1].y, py);
            if (j < 3)       B[k1] = cmul(make_float2(nx, ny), tw);
            else if (j == 3) B[k1] = rot3 ? make_float2(ny, -nx) : make_float2(nx, ny);
            else             B[k1] = make_float2(nx, ny);
        }
    }

    // lane l holds Z[k1 + 15*bitrev5(l)]
    int s = ((l&1)<<4) | ((l&2)<<2) | (l&4) | ((l&8)>>2) | ((l&16)>>4);
    float2* Z = sZ[w];
    #pragma unroll
    for (int k1 = 0; k1 < 15; k1++) Z[15*s + k1] = B[k1];
    __syncwarp();

    // ---- paired real-FFT recombination: k and 480-k together
    float* mg = smag[w];
    float2* out2 = (float2*)out;
    size_t orow = (size_t)t * FREQ;
    for (int k = l; k <= 240; k += 32){
        float2 Zk = Z[k];
        float2 Zc = Z[(480 - k) % 480];
        float Ex = Zk.x + Zc.x, Ey = Zk.y - Zc.y;
        float Ox = Zk.y + Zc.y, Oy = Zc.x - Zk.x;
        float2 rc = g_rec[k];
        float wOx = fmaf(rc.x, Ox, -rc.y*Oy);
        float wOy = fmaf(rc.x, Oy,  rc.y*Ox);
        float X1x = Ex + wOx, X1y = Ey + wOy;           // X[k]
        float X2x = Ex - wOx, X2y = wOy - Ey;           // X[480-k] = conj(E - wO)
        out2[orow + k]       = make_float2(X1x, X1y);
        out2[orow + 480 - k] = make_float2(X2x, X2y);
        float m1 = fmaf(X1x, X1x, X1y*X1y);
        float m2 = fmaf(X2x, X2x, X2y*X2y);
        mg[k]       = m1;
        mg[480 - k] = m2;
        if (k < NB_DF) g_mag[(size_t)t * NB_DF + k] = sqrtf(m1);
    }
    __syncwarp();

    // ---- erb bands
    {
        int st = c_bandOff[l], n = c_bandCnt[l];
        float acc = 0.0f;
        for (int q = 0; q < n; q++) acc += mg[st + q];
        g_erb[(size_t)t * NB_ERB + l] = 10.0f * __log10f(fmaf(acc, c_bandInv[l], 1e-10f));
    }
}

// ---------------- fused chunked scans ----------------
__global__ void pass1(int T){
    int w = blockIdx.x * blockDim.x + threadIdx.x;
    int len = T / CHUNKS;
    int totE = CHUNKS * NB_ERB;
    if (w < totE){
        int ch = w % NB_ERB, c = w / NB_ERB;
        const float* x = g_erb + (size_t)c * len * NB_ERB + ch;
        float s = 0.0f;
        for (int i = 0; i < len; i++) s = ALPHA_F * s + ONE_MINUS_ALPHA * x[i * NB_ERB];
        g_carryE[c * NB_ERB + ch] = s;
    } else if (w < totE + CHUNKS * NB_DF){
        int w2 = w - totE;
        int ch = w2 % NB_DF, c = w2 / NB_DF;
        const float* x = g_mag + (size_t)c * len * NB_DF + ch;
        float u = 0.0f;
        for (int i = 0; i < len; i++) u = ALPHA_F * u + ONE_MINUS_ALPHA * x[i * NB_DF];
        g_carryS[c * NB_DF + ch] = u;
    }
}

// parallel affine scan across chunks
__global__ __launch_bounds__(CHUNKS) void pass2(int T){
    __shared__ float sa[CHUNKS];
    __shared__ float sb[CHUNKS];
    int ch = blockIdx.x;
    int c  = threadIdx.x;
    int len = T / CHUNKS;
    float m = __powf(ALPHA_F, (float)len);
    bool isErb = (ch < NB_ERB);
    int cc = isErb ? ch : (ch - NB_ERB);
    float carry = isErb ? g_carryE[c * NB_ERB + cc] : g_carryS[c * NB_DF + cc];

    float a = m, b = carry;
    sa[c] = a; sb[c] = b;
    __syncthreads();
    #pragma unroll
    for (int off = 1; off < CHUNKS; off <<= 1){
        float pa = 0.f, pb = 0.f;
        if (c >= off){ pa = sa[c - off]; pb = sb[c - off]; }
        __syncthreads();
        if (c >= off){ b = a * pb + b; a = a * pa; }
        sa[c] = a; sb[c] = b;
        __syncthreads();
    }
    float Aex = (c == 0) ? 1.f : sa[c-1];
    float Bex = (c == 0) ? 0.f : sb[c-1];
    if (isErb){
        float s0 = -60.0f - 30.0f * (float)cc / 31.0f;
        g_inE[c * NB_ERB + cc] = Aex * s0 + Bex;
    } else {
        float u0 = 0.001f - 0.0009f * (float)cc / 95.0f;
        g_inS[c * NB_DF + cc] = Aex * u0 + Bex;
    }
}

__global__ void pass3(float* __restrict__ out, int T){
    int w = blockIdx.x * blockDim.x + threadIdx.x;
    int len = T / CHUNKS;
    int totE = CHUNKS * NB_ERB;
    if (w < totE){
        int ch = w % NB_ERB, c = w / NB_ERB;
        size_t erb_off = (size_t)T * 962;
        const float* x = g_erb + (size_t)c * len * NB_ERB + ch;
        float* o = out + erb_off + (size_t)c * len * NB_ERB + ch;
        float s = g_inE[c * NB_ERB + ch];
        for (int i = 0; i < len; i++){
            float xv = x[i * NB_ERB];
            s = ALPHA_F * s + ONE_MINUS_ALPHA * xv;
            o[i * NB_ERB] = (xv - s) * 0.025f;
        }
    } else if (w < totE + CHUNKS * NB_DF){
        int w2 = w - totE;
        int ch = w2 % NB_DF, c = w2 / NB_DF;
        size_t sf_off = (size_t)T * 962 + (size_t)T * NB_ERB;
        const float* mgp = g_mag + (size_t)c * len * NB_DF + ch;
        const float* sp = out + (size_t)c * len * 962 + 2 * ch;
        float* o = out + sf_off + (size_t)c * len * 192 + 2 * ch;
        float u = g_inS[c * NB_DF + ch];
        for (int i = 0; i < len; i++){
            u = ALPHA_F * u + ONE_MINUS_ALPHA * mgp[i * NB_DF];
            float r = rsqrtf(u);
            o[i * 192]     = sp[i * 962]     * r;
            o[i * 192 + 1] = sp[i * 962 + 1] * r;
        }
    }
}

// ---------------- launch ----------------
extern "C" void kernel_launch(void* const* d_in, const int* in_sizes, int n_in,
                              void* d_out, int out_size){
    const float* audio = (const float*)d_in[0];
    float* out = (float*)d_out;
    int T = in_sizes[0] / FRAME;
    if (T > T_MAX) T = T_MAX;
    int scanThreads = CHUNKS * (NB_ERB + NB_DF);

    fft_kernel<<<(T + 3) / 4, 128>>>(audio, out, T);
    pass1<<<(scanThreads + 255) / 256, 256>>>(T);
    pass2<<<NB_ERB + NB_DF, CHUNKS>>>(T);
    pass3<<<(scanThreads + 255) / 256, 256>>>(out, T);
}

// round 8
// speedup vs baseline: 1.0598x; 1.0598x over previous
#include <cuda_runtime.h>
#include <math.h>

#define FRAME      480
#define NHALF      480
#define FREQ       481
#define NB_ERB     32
#define NB_DF      96
#define ALPHA_F    0.99f
#define ONE_MINUS_ALPHA 0.01f
#define WNORM_F    (1.0f/960.0f)
#define T_MAX      65536
#define CHUNKS     2048
#define HALFCH     1024
#define PI_F       3.14159265358979f

// ---------------- static device tables / scratch ----------------
__device__ float2 g_tw480[15*32];
__device__ float2 g_shtw[3*32];
__device__ float2 g_win2[NHALF];
__device__ float2 g_rec[FREQ];
__device__ float  g_erb[T_MAX * NB_ERB];
__device__ float  g_mag[T_MAX * NB_DF];
__device__ float  g_carryE[CHUNKS * NB_ERB];
__device__ float  g_inE[CHUNKS * NB_ERB];
__device__ float  g_carryS[CHUNKS * NB_DF];
__device__ float  g_inS[CHUNKS * NB_DF];

__constant__ int c_bandOff[NB_ERB] =
 {0,2,4,6,8,10,12,14,16,18,20,22,24,26,31,36,43,50,58,68,80,93,108,126,146,170,198,229,266,308,358,414};
__constant__ int c_bandCnt[NB_ERB] =
 {2,2,2,2,2,2,2,2,2,2,2,2,2,5,5,7,7,8,10,12,13,15,18,20,24,28,31,37,42,50,56,67};
__constant__ float c_bandInv[NB_ERB] =
 {0.5f,0.5f,0.5f,0.5f,0.5f,0.5f,0.5f,0.5f,0.5f,0.5f,0.5f,0.5f,0.5f,
  0.2f,0.2f,1.f/7,1.f/7,0.125f,0.1f,1.f/12,1.f/13,1.f/15,1.f/18,0.05f,
  1.f/24,1.f/28,1.f/31,1.f/37,1.f/42,0.02f,1.f/56,1.f/67};

// ---------------- complex helpers ----------------
__device__ __forceinline__ float2 cmul(float2 a, float2 b){
    return make_float2(fmaf(a.x,b.x,-a.y*b.y), fmaf(a.x,b.y, a.y*b.x));
}
__device__ __forceinline__ void dft3w(float2 x0, float2 x1, float2 x2,
                                      float2& X0, float2& X1, float2& X2){
    float t1x = x1.x + x2.x, t1y = x1.y + x2.y;
    float t2x = x1.x - x2.x, t2y = x1.y - x2.y;
    X0 = make_float2(x0.x + t1x, x0.y + t1y);
    float mx = fmaf(-0.5f, t1x, x0.x), my = fmaf(-0.5f, t1y, x0.y);
    float vx = 0.86602540378f * t2x,   vy = 0.86602540378f * t2y;
    X1 = make_float2(mx + vy, my - vx);
    X2 = make_float2(mx - vy, my + vx);
}
__device__ __forceinline__ void dft5w(float2 x0, float2 x1, float2 x2, float2 x3, float2 x4,
                                      float2& X0, float2& X1, float2& X2, float2& X3, float2& X4){
    const float s1 = 0.95105651630f, s2 = 0.58778525229f;
    float t1x=x1.x+x4.x, t1y=x1.y+x4.y;
    float t2x=x1.x-x4.x, t2y=x1.y-x4.y;
    float t3x=x2.x+x3.x, t3y=x2.y+x3.y;
    float t4x=x2.x-x3.x, t4y=x2.y-x3.y;
    float t5x=t1x+t3x,   t5y=t1y+t3y;
    X0 = make_float2(x0.x+t5x, x0.y+t5y);
    float px = fmaf(-0.25f,t5x,x0.x), py = fmaf(-0.25f,t5y,x0.y);
    float t6x=t1x-t3x,   t6y=t1y-t3y;
    float qx = 0.55901699437f*t6x,    qy = 0.55901699437f*t6y;
    float Px=px+qx, Py=py+qy, Qx=px-qx, Qy=py-qy;
    float Rx = fmaf(s2,t4x, s1*t2x),  Ry = fmaf(s2,t4y, s1*t2y);
    float Sx = fmaf(-s1,t4x, s2*t2x), Sy = fmaf(-s1,t4y, s2*t2y);
    X1 = make_float2(Px+Ry, Py-Rx);
    X4 = make_float2(Px-Ry, Py+Rx);
    X2 = make_float2(Qx+Sy, Qy-Sx);
    X3 = make_float2(Qx-Sy, Qy+Sx);
}

// ---------------- init tables ----------------
__global__ void init_tables(){
    int tid = blockIdx.x * blockDim.x + threadIdx.x;
    int nth = gridDim.x * blockDim.x;
    for (int idx = tid; idx < 15*32; idx += nth){
        int k1 = idx / 32, l = idx % 32;
        float ang = -2.0f * PI_F * (float)((l * k1) % 480) / 480.0f;
        float sv, cv; sincosf(ang, &sv, &cv);
        g_tw480[idx] = make_float2(cv, sv);
    }
    for (int idx = tid; idx < 3*32; idx += nth){
        int j = idx / 32, l = idx % 32;
        int h = 16 >> j;
        float sv = 0.f, cv = 1.f;
        if (l & h){
            float ang = -2.0f * PI_F * (float)(l & (h-1)) / (float)(2*h);
            sincosf(ang, &sv, &cv);
        }
        g_shtw[idx] = make_float2(cv, sv);
    }
    for (int j = tid; j < NHALF; j += nth){
        float a0 = sinf(0.5f * PI_F * (2*j + 0.5f) / 480.0f);
        float a1 = sinf(0.5f * PI_F * (2*j + 1.5f) / 480.0f);
        const float s = 0.5f * WNORM_F;
        g_win2[j] = make_float2(s * sinf(0.5f * PI_F * a0 * a0),
                                s * sinf(0.5f * PI_F * a1 * a1));
    }
    for (int k = tid; k < FREQ; k += nth){
        float ang = -PI_F * (float)k / 480.0f;
        float sv, cv; sincosf(ang, &sv, &cv);
        g_rec[k] = make_float2(cv, sv);
    }
}

// ---------------- FFT: one warp per frame, register-resident ----------------
__global__ __launch_bounds__(128) void fft_kernel(const float* __restrict__ audio,
                                                  float* __restrict__ out, int T){
    __shared__ float2 sZ[4][NHALF];
    __shared__ float  smag[4][FREQ];
    int w = threadIdx.x >> 5;
    int l = threadIdx.x & 31;
    int t = blockIdx.x * 4 + w;
    if (t >= T) return;

    const float2* audio2 = (const float2*)audio;
    long base2 = ((long)t - 1) * 240;

    float2 z[15];
    #pragma unroll
    for (int m = 0; m < 15; m++){
        long i2 = base2 + l + 32*m;
        float2 x = (i2 >= 0) ? audio2[i2] : make_float2(0.f,0.f);
        float2 ww = g_win2[l + 32*m];
        z[m] = make_float2(x.x*ww.x, x.y*ww.y);
    }

    float2 B[15];
    {
        float2 G0[5], G1[5], G2[5];
        #pragma unroll
        for (int b = 0; b < 5; b++)
            dft3w(z[b], z[5+b], z[10+b], G0[b], G1[b], G2[b]);
        dft5w(G0[0],G0[1],G0[2],G0[3],G0[4], B[0],B[3],B[6],B[9],B[12]);
        G1[1] = cmul(G1[1], make_float2( 0.91354545764f,-0.40673664308f));
        G1[2] = cmul(G1[2], make_float2( 0.66913060636f,-0.74314482548f));
        G1[3] = cmul(G1[3], make_float2( 0.30901699437f,-0.95105651630f));
        G1[4] = cmul(G1[4], make_float2(-0.10452846327f,-0.99452189537f));
        dft5w(G1[0],G1[1],G1[2],G1[3],G1[4], B[1],B[4],B[7],B[10],B[13]);
        G2[1] = cmul(G2[1], make_float2( 0.66913060636f,-0.74314482548f));
        G2[2] = cmul(G2[2], make_float2(-0.10452846327f,-0.99452189537f));
        G2[3] = cmul(G2[3], make_float2(-0.80901699437f,-0.58778525229f));
        G2[4] = cmul(G2[4], make_float2(-0.97814760073f, 0.20791169082f));
        dft5w(G2[0],G2[1],G2[2],G2[3],G2[4], B[2],B[5],B[8],B[11],B[14]);
    }

    #pragma unroll
    for (int k1 = 1; k1 < 15; k1++)
        B[k1] = cmul(B[k1], g_tw480[k1*32 + l]);

    bool rot3 = ((l & 3) == 3);
    #pragma unroll
    for (int j = 0; j < 5; j++){
        int h = 16 >> j;
        float sgn = (l & h) ? -1.f : 1.f;
        float2 tw = (j < 3) ? g_shtw[j*32 + l] : make_float2(1.f, 0.f);
        #pragma unroll
        for (int k1 = 0; k1 < 15; k1++){
            float px = __shfl_xor_sync(0xffffffffu, B[k1].x, h);
            float py = __shfl_xor_sync(0xffffffffu, B[k1].y, h);
            float nx = fmaf(sgn, B[k1].x, px), ny = fmaf(sgn, B[k1].y, py);
            if (j < 3)       B[k1] = cmul(make_float2(nx, ny), tw);
            else if (j == 3) B[k1] = rot3 ? make_float2(ny, -nx) : make_float2(nx, ny);
            else             B[k1] = make_float2(nx, ny);
        }
    }

    int s = ((l&1)<<4) | ((l&2)<<2) | (l&4) | ((l&8)>>2) | ((l&16)>>4);
    float2* Z = sZ[w];
    #pragma unroll
    for (int k1 = 0; k1 < 15; k1++) Z[15*s + k1] = B[k1];
    __syncwarp();

    float* mg = smag[w];
    float2* out2 = (float2*)out;
    size_t orow = (size_t)t * FREQ;
    for (int k = l; k <= 240; k += 32){
        float2 Zk = Z[k];
        float2 Zc = Z[(480 - k) % 480];
        float Ex = Zk.x + Zc.x, Ey = Zk.y - Zc.y;
        float Ox = Zk.y + Zc.y, Oy = Zc.x - Zk.x;
        float2 rc = g_rec[k];
        float wOx = fmaf(rc.x, Ox, -rc.y*Oy);
        float wOy = fmaf(rc.x, Oy,  rc.y*Ox);
        float X1x = Ex + wOx, X1y = Ey + wOy;
        float X2x = Ex - wOx, X2y = wOy - Ey;
        out2[orow + k]       = make_float2(X1x, X1y);
        out2[orow + 480 - k] = make_float2(X2x, X2y);
        float m1 = fmaf(X1x, X1x, X1y*X1y);
        float m2 = fmaf(X2x, X2x, X2y*X2y);
        mg[k]       = m1;
        mg[480 - k] = m2;
        if (k < NB_DF) g_mag[(size_t)t * NB_DF + k] = sqrtf(m1);
    }
    __syncwarp();

    {
        int st = c_bandOff[l], n = c_bandCnt[l];
        float acc = 0.0f;
        for (int q = 0; q < n; q++) acc += mg[st + q];
        g_erb[(size_t)t * NB_ERB + l] = 10.0f * __log10f(fmaf(acc, c_bandInv[l], 1e-10f));
    }
}

// ---------------- chunked scans: pass1 ----------------
__global__ void pass1(int T){
    int w = blockIdx.x * blockDim.x + threadIdx.x;
    int len = T / CHUNKS;
    int totE = CHUNKS * NB_ERB;
    if (w < totE){
        int ch = w % NB_ERB, c = w / NB_ERB;
        const float* x = g_erb + (size_t)c * len * NB_ERB + ch;
        float s = 0.0f;
        for (int i = 0; i < len; i++) s = ALPHA_F * s + ONE_MINUS_ALPHA * x[i * NB_ERB];
        g_carryE[c * NB_ERB + ch] = s;
    } else if (w < totE + CHUNKS * NB_DF){
        int w2 = w - totE;
        int ch = w2 % NB_DF, c = w2 / NB_DF;
        const float* x = g_mag + (size_t)c * len * NB_DF + ch;
        float u = 0.0f;
        for (int i = 0; i < len; i++) u = ALPHA_F * u + ONE_MINUS_ALPHA * x[i * NB_DF];
        g_carryS[c * NB_DF + ch] = u;
    }
}

// ---------------- pass2: 2048 chunks, 1024 threads compose pairs ----------------
__global__ __launch_bounds__(HALFCH) void pass2(int T){
    __shared__ float sa[HALFCH];
    __shared__ float sb[HALFCH];
    int ch = blockIdx.x;
    int c  = threadIdx.x;        // pair index: chunks 2c, 2c+1
    int len = T / CHUNKS;
    float m = __powf(ALPHA_F, (float)len);
    bool isErb = (ch < NB_ERB);
    int cc = isErb ? ch : (ch - NB_ERB);
    float cr0 = isErb ? g_carryE[(2*c)   * NB_ERB + cc] : g_carryS[(2*c)   * NB_DF + cc];
    float cr1 = isErb ? g_carryE[(2*c+1) * NB_ERB + cc] : g_carryS[(2*c+1) * NB_DF + cc];

    // composite of the pair: a = m^2, b = m*cr0 + cr1
    float a = m * m, b = fmaf(m, cr0, cr1);
    sa[c] = a; sb[c] = b;
    __syncthreads();
    #pragma unroll
    for (int off = 1; off < HALFCH; off <<= 1){
        float pa = 0.f, pb = 0.f;
        if (c >= off){ pa = sa[c - off]; pb = sb[c - off]; }
        __syncthreads();
        if (c >= off){ b = a * pb + b; a = a * pa; }
        sa[c] = a; sb[c] = b;
        __syncthreads();
    }
    float Aex = (c == 0) ? 1.f : sa[c-1];
    float Bex = (c == 0) ? 0.f : sb[c-1];
    if (isErb){
        float s0 = -60.0f - 30.0f * (float)cc / 31.0f;
        float st0 = Aex * s0 + Bex;                    // state entering chunk 2c
        g_inE[(2*c)   * NB_ERB + cc] = st0;
        g_inE[(2*c+1) * NB_ERB + cc] = fmaf(m, st0, cr0);
    } else {
        float u0 = 0.001f - 0.0009f * (float)cc / 95.0f;
        float st0 = Aex * u0 + Bex;
        g_inS[(2*c)   * NB_DF + cc] = st0;
        g_inS[(2*c+1) * NB_DF + cc] = fmaf(m, st0, cr0);
    }
}

// ---------------- pass3 ----------------
__global__ void pass3(float* __restrict__ out, int T){
    int w = blockIdx.x * blockDim.x + threadIdx.x;
    int len = T / CHUNKS;
    int totE = CHUNKS * NB_ERB;
    if (w < totE){
        int ch = w % NB_ERB, c = w / NB_ERB;
        size_t erb_off = (size_t)T * 962;
        const float* x = g_erb + (size_t)c * len * NB_ERB + ch;
        float* o = out + erb_off + (size_t)c * len * NB_ERB + ch;
        float s = g_inE[c * NB_ERB + ch];
        for (int i = 0; i < len; i++){
            float xv = x[i * NB_ERB];
            s = ALPHA_F * s + ONE_MINUS_ALPHA * xv;
            o[i * NB_ERB] = (xv - s) * 0.025f;
        }
    } else if (w < totE + CHUNKS * NB_DF){
        int w2 = w - totE;
        int ch = w2 % NB_DF, c = w2 / NB_DF;
        const float* mgp = g_mag + (size_t)c * len * NB_DF + ch;
        const float2* sp2 = (const float2*)out + (size_t)c * len * FREQ + ch;
        float2* o2 = (float2*)(out + (size_t)T * 962 + (size_t)T * NB_ERB)
                     + (size_t)c * len * NB_DF + ch;
        float u = g_inS[c * NB_DF + ch];
        for (int i = 0; i < len; i++){
            u = ALPHA_F * u + ONE_MINUS_ALPHA * mgp[i * NB_DF];
            float r = rsqrtf(u);
            float2 sv = sp2[i * FREQ];
            o2[i * NB_DF] = make_float2(sv.x * r, sv.y * r);
        }
    }
}

// ---------------- launch ----------------
extern "C" void kernel_launch(void* const* d_in, const int* in_sizes, int n_in,
                              void* d_out, int out_size){
    const float* audio = (const float*)d_in[0];
    float* out = (float*)d_out;
    int T = in_sizes[0] / FRAME;
    if (T > T_MAX) T = T_MAX;
    int scanThreads = CHUNKS * (NB_ERB + NB_DF);

    init_tables<<<8, 256>>>();
    fft_kernel<<<(T + 3) / 4, 128>>>(audio, out, T);
    pass1<<<(scanThreads + 255) / 256, 256>>>(T);
    pass2<<<NB_ERB + NB_DF, HALFCH>>>(T);
    pass3<<<(scanThreads + 255) / 256, 256>>>(out, T);
}

// round 9
// speedup vs baseline: 1.0758x; 1.0152x over previous
#include <cuda_runtime.h>
#include <math.h>

#define FRAME      480
#define NHALF      480
#define FREQ       481
#define NB_ERB     32
#define NB_DF      96
#define ALPHA_F    0.99f
#define ONE_MINUS_ALPHA 0.01f
#define WNORM_F    (1.0f/960.0f)
#define T_MAX      65536
#define CHUNKS     2048
#define HALFCH     1024
#define PI_F       3.14159265358979f

typedef unsigned long long ull;

// ---------------- packed f32x2 primitives ----------------
__device__ __forceinline__ ull pk(float x, float y){ ull r; asm("mov.b64 %0, {%1, %2};" : "=l"(r) : "f"(x), "f"(y)); return r; }
__device__ __forceinline__ void up(ull a, float& x, float& y){ asm("mov.b64 {%0, %1}, %2;" : "=f"(x), "=f"(y) : "l"(a)); }
__device__ __forceinline__ ull padd(ull a, ull b){ ull r; asm("add.rn.f32x2 %0, %1, %2;" : "=l"(r) : "l"(a), "l"(b)); return r; }
__device__ __forceinline__ ull psub(ull a, ull b){ ull r; asm("sub.rn.f32x2 %0, %1, %2;" : "=l"(r) : "l"(a), "l"(b)); return r; }
__device__ __forceinline__ ull pmul(ull a, ull b){ ull r; asm("mul.rn.f32x2 %0, %1, %2;" : "=l"(r) : "l"(a), "l"(b)); return r; }
__device__ __forceinline__ ull pfma(ull a, ull b, ull c){ ull r; asm("fma.rn.f32x2 %0, %1, %2, %3;" : "=l"(r) : "l"(a), "l"(b), "l"(c)); return r; }

// packed complex mul by immediate constant (c + i s), frame-pairwise
__device__ __forceinline__ void cmulc2(ull& re, ull& im, float c, float s){
    ull C = pk(c, c), S = pk(s, s);
    ull nr = psub(pmul(re, C), pmul(im, S));
    ull ni = pfma(im, C, pmul(re, S));
    re = nr; im = ni;
}

// ---------------- static device tables / scratch ----------------
__device__ float4 g_tw480[15*32];      // (c,c,s,s): W_480^{l*k1}, [k1*32+l]
__device__ float2 g_shtw[3*32];
__device__ float2 g_win2[NHALF];       // window pairs, prescaled by 0.5*WNORM
__device__ float2 g_rec[FREQ];
__device__ float  g_erb[T_MAX * NB_ERB];
__device__ float  g_mag[T_MAX * NB_DF];
__device__ float  g_carryE[CHUNKS * NB_ERB];
__device__ float  g_inE[CHUNKS * NB_ERB];
__device__ float  g_carryS[CHUNKS * NB_DF];
__device__ float  g_inS[CHUNKS * NB_DF];

__constant__ int c_bandOff[NB_ERB] =
 {0,2,4,6,8,10,12,14,16,18,20,22,24,26,31,36,43,50,58,68,80,93,108,126,146,170,198,229,266,308,358,414};
__constant__ int c_bandCnt[NB_ERB] =
 {2,2,2,2,2,2,2,2,2,2,2,2,2,5,5,7,7,8,10,12,13,15,18,20,24,28,31,37,42,50,56,67};
__constant__ float c_bandInv[NB_ERB] =
 {0.5f,0.5f,0.5f,0.5f,0.5f,0.5f,0.5f,0.5f,0.5f,0.5f,0.5f,0.5f,0.5f,
  0.2f,0.2f,1.f/7,1.f/7,0.125f,0.1f,1.f/12,1.f/13,1.f/15,1.f/18,0.05f,
  1.f/24,1.f/28,1.f/31,1.f/37,1.f/42,0.02f,1.f/56,1.f/67};

// ---------------- packed Winograd DFTs (2 frames per lane) ----------------
__device__ __forceinline__ void dft3p2(ull x0r, ull x0i, ull x1r, ull x1i, ull x2r, ull x2i,
                                       ull& X0r, ull& X0i, ull& X1r, ull& X1i, ull& X2r, ull& X2i){
    ull Ch = pk(-0.5f,-0.5f), C8 = pk(0.86602540378f,0.86602540378f);
    ull t1r = padd(x1r,x2r), t1i = padd(x1i,x2i);
    ull t2r = psub(x1r,x2r), t2i = psub(x1i,x2i);
    X0r = padd(x0r,t1r); X0i = padd(x0i,t1i);
    ull mr = pfma(Ch,t1r,x0r), mi = pfma(Ch,t1i,x0i);
    ull vr = pmul(C8,t2r),     vi = pmul(C8,t2i);
    X1r = padd(mr,vi); X1i = psub(mi,vr);
    X2r = psub(mr,vi); X2i = padd(mi,vr);
}
__device__ __forceinline__ void dft5p2(ull x0r, ull x0i, ull x1r, ull x1i, ull x2r, ull x2i,
                                       ull x3r, ull x3i, ull x4r, ull x4i,
                                       ull& X0r, ull& X0i, ull& X1r, ull& X1i, ull& X2r, ull& X2i,
                                       ull& X3r, ull& X3i, ull& X4r, ull& X4i){
    ull Cq = pk(-0.25f,-0.25f), C5 = pk(0.55901699437f,0.55901699437f);
    ull Cs1 = pk(0.95105651630f,0.95105651630f), Cs2 = pk(0.58778525229f,0.58778525229f);
    ull Cs1n = pk(-0.95105651630f,-0.95105651630f);
    ull t1r=padd(x1r,x4r), t1i=padd(x1i,x4i);
    ull t2r=psub(x1r,x4r), t2i=psub(x1i,x4i);
    ull t3r=padd(x2r,x3r), t3i=padd(x2i,x3i);
    ull t4r=psub(x2r,x3r), t4i=psub(x2i,x3i);
    ull t5r=padd(t1r,t3r), t5i=padd(t1i,t3i);
    X0r = padd(x0r,t5r); X0i = padd(x0i,t5i);
    ull pr = pfma(Cq,t5r,x0r), pi = pfma(Cq,t5i,x0i);
    ull t6r=psub(t1r,t3r), t6i=psub(t1i,t3i);
    ull qr = pmul(C5,t6r), qi = pmul(C5,t6i);
    ull Pr=padd(pr,qr), Pi=padd(pi,qi), Qr=psub(pr,qr), Qi=psub(pi,qi);
    ull Rr = pfma(Cs2,t4r,pmul(Cs1,t2r)), Ri = pfma(Cs2,t4i,pmul(Cs1,t2i));
    ull Sr = pfma(Cs1n,t4r,pmul(Cs2,t2r)), Si = pfma(Cs1n,t4i,pmul(Cs2,t2i));
    X1r=padd(Pr,Ri); X1i=psub(Pi,Rr);
    X4r=psub(Pr,Ri); X4i=padd(Pi,Rr);
    X2r=padd(Qr,Si); X2i=psub(Qi,Sr);
    X3r=psub(Qr,Si); X3i=padd(Qi,Sr);
}

// ---------------- init tables ----------------
__global__ void init_tables(){
    int tid = blockIdx.x * blockDim.x + threadIdx.x;
    int nth = gridDim.x * blockDim.x;
    for (int idx = tid; idx < 15*32; idx += nth){
        int k1 = idx / 32, l = idx % 32;
        float ang = -2.0f * PI_F * (float)((l * k1) % 480) / 480.0f;
        float sv, cv; sincosf(ang, &sv, &cv);
        g_tw480[idx] = make_float4(cv, cv, sv, sv);
    }
    for (int idx = tid; idx < 3*32; idx += nth){
        int j = idx / 32, l = idx % 32;
        int h = 16 >> j;
        float sv = 0.f, cv = 1.f;
        if (l & h){
            float ang = -2.0f * PI_F * (float)(l & (h-1)) / (float)(2*h);
            sincosf(ang, &sv, &cv);
        }
        g_shtw[idx] = make_float2(cv, sv);
    }
    for (int j = tid; j < NHALF; j += nth){
        float a0 = sinf(0.5f * PI_F * (2*j + 0.5f) / 480.0f);
        float a1 = sinf(0.5f * PI_F * (2*j + 1.5f) / 480.0f);
        const float s = 0.5f * WNORM_F;
        g_win2[j] = make_float2(s * sinf(0.5f * PI_F * a0 * a0),
                                s * sinf(0.5f * PI_F * a1 * a1));
    }
    for (int k = tid; k < FREQ; k += nth){
        float ang = -PI_F * (float)k / 480.0f;
        float sv, cv; sincosf(ang, &sv, &cv);
        g_rec[k] = make_float2(cv, sv);
    }
}

// ---------------- scalar epilogue: recombination + erb for one frame ----------------
__device__ __forceinline__ void epilogue_frame(const float2* __restrict__ Z, float* __restrict__ mg,
                                               float2* __restrict__ out2, int t, int l){
    size_t orow = (size_t)t * FREQ;
    for (int k = l; k <= 240; k += 32){
        float2 Zk = Z[k];
        float2 Zc = Z[(480 - k) % 480];
        float Ex = Zk.x + Zc.x, Ey = Zk.y - Zc.y;
        float Ox = Zk.y + Zc.y, Oy = Zc.x - Zk.x;
        float2 rc = g_rec[k];
        float wOx = fmaf(rc.x, Ox, -rc.y*Oy);
        float wOy = fmaf(rc.x, Oy,  rc.y*Ox);
        float X1x = Ex + wOx, X1y = Ey + wOy;
        float X2x = Ex - wOx, X2y = wOy - Ey;
        out2[orow + k]       = make_float2(X1x, X1y);
        out2[orow + 480 - k] = make_float2(X2x, X2y);
        float m1 = fmaf(X1x, X1x, X1y*X1y);
        float m2 = fmaf(X2x, X2x, X2y*X2y);
        mg[k]       = m1;
        mg[480 - k] = m2;
        if (k < NB_DF) g_mag[(size_t)t * NB_DF + k] = sqrtf(m1);
    }
    __syncwarp();
    {
        int st = c_bandOff[l], n = c_bandCnt[l];
        float acc = 0.0f;
        for (int q = 0; q < n; q++) acc += mg[st + q];
        g_erb[(size_t)t * NB_ERB + l] = 10.0f * __log10f(fmaf(acc, c_bandInv[l], 1e-10f));
    }
}

// ---------------- FFT: one warp per FRAME-PAIR, f32x2 packed ----------------
__global__ __launch_bounds__(128) void fft_kernel(const float* __restrict__ audio,
                                                  float* __restrict__ out, int T){
    __shared__ float2 sZ[4][NHALF];
    __shared__ float  smag[4][FREQ];
    int w = threadIdx.x >> 5;
    int l = threadIdx.x & 31;
    int g = blockIdx.x * 4 + w;
    int ta = 2 * g;
    if (ta >= T) return;
    bool liveB = (ta + 1 < T);

    const float2* audio2 = (const float2*)audio;
    long baseA = ((long)ta - 1) * 240;     // frame a window start (float2 units)
    long baseB = baseA + 240;              // frame b window start

    // load + window: packed (frame a, frame b)
    ull re[15], im[15];
    #pragma unroll
    for (int m = 0; m < 15; m++){
        int n = l + 32*m;
        long iA = baseA + n, iB = baseB + n;
        float2 xa = (iA >= 0) ? audio2[iA] : make_float2(0.f,0.f);
        float2 xb = (liveB)  ? audio2[iB] : make_float2(0.f,0.f);
        float2 ww = g_win2[n];
        re[m] = pmul(pk(xa.x, xb.x), pk(ww.x, ww.x));
        im[m] = pmul(pk(xa.y, xb.y), pk(ww.y, ww.y));
    }

    // ---- radix-15 (3x5 Winograd), packed
    ull Br[15], Bi[15];
    {
        ull G0r[5], G0i[5], G1r[5], G1i[5], G2r[5], G2i[5];
        #pragma unroll
        for (int b = 0; b < 5; b++)
            dft3p2(re[b],im[b], re[5+b],im[5+b], re[10+b],im[10+b],
                   G0r[b],G0i[b], G1r[b],G1i[b], G2r[b],G2i[b]);
        dft5p2(G0r[0],G0i[0],G0r[1],G0i[1],G0r[2],G0i[2],G0r[3],G0i[3],G0r[4],G0i[4],
               Br[0],Bi[0], Br[3],Bi[3], Br[6],Bi[6], Br[9],Bi[9], Br[12],Bi[12]);
        cmulc2(G1r[1],G1i[1],  0.91354545764f,-0.40673664308f);
        cmulc2(G1r[2],G1i[2],  0.66913060636f,-0.74314482548f);
        cmulc2(G1r[3],G1i[3],  0.30901699437f,-0.95105651630f);
        cmulc2(G1r[4],G1i[4], -0.10452846327f,-0.99452189537f);
        dft5p2(G1r[0],G1i[0],G1r[1],G1i[1],G1r[2],G1i[2],G1r[3],G1i[3],G1r[4],G1i[4],
               Br[1],Bi[1], Br[4],Bi[4], Br[7],Bi[7], Br[10],Bi[10], Br[13],Bi[13]);
        cmulc2(G2r[1],G2i[1],  0.66913060636f,-0.74314482548f);
        cmulc2(G2r[2],G2i[2], -0.10452846327f,-0.99452189537f);
        cmulc2(G2r[3],G2i[3], -0.80901699437f,-0.58778525229f);
        cmulc2(G2r[4],G2i[4], -0.97814760073f, 0.20791169082f);
        dft5p2(G2r[0],G2i[0],G2r[1],G2i[1],G2r[2],G2i[2],G2r[3],G2i[3],G2r[4],G2i[4],
               Br[2],Bi[2], Br[5],Bi[5], Br[8],Bi[8], Br[11],Bi[11], Br[14],Bi[14]);
    }

    // ---- four-step twiddle (table (c,c,s,s))
    #pragma unroll
    for (int k1 = 1; k1 < 15; k1++){
        float4 tw = g_tw480[k1*32 + l];
        ull C = pk(tw.x, tw.y), S = pk(tw.z, tw.w);
        ull nr = psub(pmul(Br[k1], C), pmul(Bi[k1], S));
        ull ni = pfma(Bi[k1], C, pmul(Br[k1], S));
        Br[k1] = nr; Bi[k1] = ni;
    }

    // ---- 32-pt cross-lane DFT: 5 radix-2 DIF shuffle stages, packed
    bool rot3 = ((l & 3) == 3);
    ull NEG1 = pk(-1.f, -1.f);
    #pragma unroll
    for (int j = 0; j < 5; j++){
        int h = 16 >> j;
        float sgn = (l & h) ? -1.f : 1.f;
        ull sgn2 = pk(sgn, sgn);
        ull C = 0, S = 0, Sn = 0;
        if (j < 3){
            float2 tw = g_shtw[j*32 + l];
            C = pk(tw.x, tw.x); S = pk(tw.y, tw.y); Sn = pk(-tw.y, -tw.y);
        }
        #pragma unroll
        for (int k1 = 0; k1 < 15; k1++){
            float ra, rb, ia, ib;
            up(Br[k1], ra, rb); up(Bi[k1], ia, ib);
            float pra = __shfl_xor_sync(0xffffffffu, ra, h);
            float prb = __shfl_xor_sync(0xffffffffu, rb, h);
            float pia = __shfl_xor_sync(0xffffffffu, ia, h);
            float pib = __shfl_xor_sync(0xffffffffu, ib, h);
            ull nr = pfma(sgn2, Br[k1], pk(pra, prb));
            ull ni = pfma(sgn2, Bi[k1], pk(pia, pib));
            if (j < 3){
                Br[k1] = pfma(ni, Sn, pmul(nr, C));
                Bi[k1] = pfma(ni, C,  pmul(nr, S));
            } else if (j == 3){
                Br[k1] = rot3 ? ni : nr;
                Bi[k1] = rot3 ? pmul(NEG1, nr) : ni;
            } else {
                Br[k1] = nr; Bi[k1] = ni;
            }
        }
    }

    // lane l holds Z[k1 + 15*bitrev5(l)] for both frames
    int s = ((l&1)<<4) | ((l&2)<<2) | (l&4) | ((l&8)>>2) | ((l&16)>>4);
    float2* Z = sZ[w];
    float* mg = smag[w];
    float2* out2 = (float2*)out;

    // ---- frame a
    #pragma unroll
    for (int k1 = 0; k1 < 15; k1++){
        float ra, rb, ia, ib;
        up(Br[k1], ra, rb); up(Bi[k1], ia, ib);
        Z[15*s + k1] = make_float2(ra, ia);
    }
    __syncwarp();
    epilogue_frame(Z, mg, out2, ta, l);
    __syncwarp();

    // ---- frame b
    if (liveB){
        #pragma unroll
        for (int k1 = 0; k1 < 15; k1++){
            float ra, rb, ia, ib;
            up(Br[k1], ra, rb); up(Bi[k1], ia, ib);
            Z[15*s + k1] = make_float2(rb, ib);
        }
        __syncwarp();
        epilogue_frame(Z, mg, out2, ta + 1, l);
    }
}

// ---------------- chunked scans ----------------
__global__ void pass1(int T){
    int w = blockIdx.x * blockDim.x + threadIdx.x;
    int len = T / CHUNKS;
    int totE = CHUNKS * NB_ERB;
    if (w < totE){
        int ch = w % NB_ERB, c = w / NB_ERB;
        const float* x = g_erb + (size_t)c * len * NB_ERB + ch;
        float s = 0.0f;
        for (int i = 0; i < len; i++) s = ALPHA_F * s + ONE_MINUS_ALPHA * x[i * NB_ERB];
        g_carryE[c * NB_ERB + ch] = s;
    } else if (w < totE + CHUNKS * NB_DF){
        int w2 = w - totE;
        int ch = w2 % NB_DF, c = w2 / NB_DF;
        const float* x = g_mag + (size_t)c * len * NB_DF + ch;
        float u = 0.0f;
        for (int i = 0; i < len; i++) u = ALPHA_F * u + ONE_MINUS_ALPHA * x[i * NB_DF];
        g_carryS[c * NB_DF + ch] = u;
    }
}

__global__ __launch_bounds__(HALFCH) void pass2(int T){
    __shared__ float sa[HALFCH];
    __shared__ float sb[HALFCH];
    int ch = blockIdx.x;
    int c  = threadIdx.x;
    int len = T / CHUNKS;
    float m = __powf(ALPHA_F, (float)len);
    bool isErb = (ch < NB_ERB);
    int cc = isErb ? ch : (ch - NB_ERB);
    float cr0 = isErb ? g_carryE[(2*c)   * NB_ERB + cc] : g_carryS[(2*c)   * NB_DF + cc];
    float cr1 = isErb ? g_carryE[(2*c+1) * NB_ERB + cc] : g_carryS[(2*c+1) * NB_DF + cc];

    float a = m * m, b = fmaf(m, cr0, cr1);
    sa[c] = a; sb[c] = b;
    __syncthreads();
    #pragma unroll
    for (int off = 1; off < HALFCH; off <<= 1){
        float pa = 0.f, pb = 0.f;
        if (c >= off){ pa = sa[c - off]; pb = sb[c - off]; }
        __syncthreads();
        if (c >= off){ b = a * pb + b; a = a * pa; }
        sa[c] = a; sb[c] = b;
        __syncthreads();
    }
    float Aex = (c == 0) ? 1.f : sa[c-1];
    float Bex = (c == 0) ? 0.f : sb[c-1];
    if (isErb){
        float s0 = -60.0f - 30.0f * (float)cc / 31.0f;
        float st0 = Aex * s0 + Bex;
        g_inE[(2*c)   * NB_ERB + cc] = st0;
        g_inE[(2*c+1) * NB_ERB + cc] = fmaf(m, st0, cr0);
    } else {
        float u0 = 0.001f - 0.0009f * (float)cc / 95.0f;
        float st0 = Aex * u0 + Bex;
        g_inS[(2*c)   * NB_DF + cc] = st0;
        g_inS[(2*c+1) * NB_DF + cc] = fmaf(m, st0, cr0);
    }
}

__global__ void pass3(float* __restrict__ out, int T){
    int w = blockIdx.x * blockDim.x + threadIdx.x;
    int len = T / CHUNKS;
    int totE = CHUNKS * NB_ERB;
    if (w < totE){
        int ch = w % NB_ERB, c = w / NB_ERB;
        size_t erb_off = (size_t)T * 962;
        const float* x = g_erb + (size_t)c * len * NB_ERB + ch;
        float* o = out + erb_off + (size_t)c * len * NB_ERB + ch;
        float s = g_inE[c * NB_ERB + ch];
        for (int i = 0; i < len; i++){
            float xv = x[i * NB_ERB];
            s = ALPHA_F * s + ONE_MINUS_ALPHA * xv;
            o[i * NB_ERB] = (xv - s) * 0.025f;
        }
    } else if (w < totE + CHUNKS * NB_DF){
        int w2 = w - totE;
        int ch = w2 % NB_DF, c = w2 / NB_DF;
        const float* mgp = g_mag + (size_t)c * len * NB_DF + ch;
        const float2* sp2 = (const float2*)out + (size_t)c * len * FREQ + ch;
        float2* o2 = (float2*)(out + (size_t)T * 962 + (size_t)T * NB_ERB)
                     + (size_t)c * len * NB_DF + ch;
        float u = g_inS[c * NB_DF + ch];
        for (int i = 0; i < len; i++){
            u = ALPHA_F * u + ONE_MINUS_ALPHA * mgp[i * NB_DF];
            float r = rsqrtf(u);
            float2 sv = sp2[i * FREQ];
            o2[i * NB_DF] = make_float2(sv.x * r, sv.y * r);
        }
    }
}

// ---------------- launch ----------------
extern "C" void kernel_launch(void* const* d_in, const int* in_sizes, int n_in,
                              void* d_out, int out_size){
    const float* audio = (const float*)d_in[0];
    float* out = (float*)d_out;
    int T = in_sizes[0] / FRAME;
    if (T > T_MAX) T = T_MAX;
    int scanThreads = CHUNKS * (NB_ERB + NB_DF);
    int nPairs = (T + 1) / 2;

    init_tables<<<8, 256>>>();
    fft_kernel<<<(nPairs + 3) / 4, 128>>>(audio, out, T);
    pass1<<<(scanThreads + 255) / 256, 256>>>(T);
    pass2<<<NB_ERB + NB_DF, HALFCH>>>(T);
    pass3<<<(scanThreads + 255) / 256, 256>>>(out, T);
}